// round 13
// baseline (speedup 1.0000x reference)
#include <cuda_runtime.h>
#include <cuda_bf16.h>
#include <math.h>
#include <stdint.h>

#define EMB   1024
#define SEQ   2048
#define BATCH 2
#define MTOK  (BATCH*SEQ)   // 4096
#define FF    4096
#define HEADS 16
#define HD    64
#define QKS   3072          // fused qkv col count

// ---------------- arena ------------------------------------------------------
#define SLOT    ((size_t)MTOK*EMB)
#define HSLOT   (SLOT/2)
#define FSLOT   ((size_t)MTOK*FF/2)
#define PLANE_Q 1572864ull
#define PLANE_E 524288ull
#define PLANE_F 2097152ull
#define OF_X1   (SLOT*3)
#define OF_HB   (SLOT*4)
#define OF_FFN  (OF_HB + HSLOT*6)
#define OF_WT   (OF_FFN + FSLOT*2)
__device__ float g_arena[OF_WT + 2ull*PLANE_Q + 2ull*PLANE_E + 4ull*PLANE_F];

// ---------------- helpers ----------------------------------------------------
__device__ __forceinline__ void split2(float x0, float x1, uint32_t& hi, uint32_t& lo)
{
    __nv_bfloat16 h0 = __float2bfloat16(x0);
    __nv_bfloat16 h1 = __float2bfloat16(x1);
    __nv_bfloat16 l0 = __float2bfloat16(x0 - __bfloat162float(h0));
    __nv_bfloat16 l1 = __float2bfloat16(x1 - __bfloat162float(h1));
    hi = (uint32_t)__bfloat16_as_ushort(h0) | ((uint32_t)__bfloat16_as_ushort(h1) << 16);
    lo = (uint32_t)__bfloat16_as_ushort(l0) | ((uint32_t)__bfloat16_as_ushort(l1) << 16);
}

__device__ __forceinline__ float gelu_f(float x)
{
    float x3 = x*x*x;
    float t  = tanhf(0.7978845608028654f*(x + 0.044715f*x3));
    return 0.5f*x*(1.0f + t);
}

__device__ __forceinline__ uint32_t smem_u32(const void* p)
{
    return (uint32_t)__cvta_generic_to_shared(p);
}

#define CP16(dst, src) \
    asm volatile("cp.async.cg.shared.global [%0], [%1], 16;\n" :: "r"(dst), "l"(src))
#define CP_COMMIT() asm volatile("cp.async.commit_group;\n" ::: "memory")
#define CP_WAIT0()  asm volatile("cp.async.wait_group 0;\n" ::: "memory")
#define CP_WAIT1()  asm volatile("cp.async.wait_group 1;\n" ::: "memory")
#define CP_WAIT2()  asm volatile("cp.async.wait_group 2;\n" ::: "memory")

__device__ __forceinline__ void mma16816(float* c, const uint32_t* a, const uint32_t* b)
{
    asm volatile(
        "mma.sync.aligned.m16n8k16.row.col.f32.bf16.bf16.f32 "
        "{%0,%1,%2,%3},{%4,%5,%6,%7},{%8,%9},{%0,%1,%2,%3};"
        : "+f"(c[0]), "+f"(c[1]), "+f"(c[2]), "+f"(c[3])
        : "r"(a[0]), "r"(a[1]), "r"(a[2]), "r"(a[3]), "r"(b[0]), "r"(b[1]));
}

__device__ __forceinline__ void ldsm4(uint32_t& r0, uint32_t& r1, uint32_t& r2,
                                      uint32_t& r3, uint32_t addr)
{
    asm volatile("ldmatrix.sync.aligned.m8n8.x4.shared.b16 {%0,%1,%2,%3}, [%4];"
        : "=r"(r0), "=r"(r1), "=r"(r2), "=r"(r3) : "r"(addr));
}

__device__ __forceinline__ void ldsm4t(uint32_t& r0, uint32_t& r1, uint32_t& r2,
                                       uint32_t& r3, uint32_t addr)
{
    asm volatile("ldmatrix.sync.aligned.m8n8.x4.trans.shared.b16 {%0,%1,%2,%3}, [%4];"
        : "=r"(r0), "=r"(r1), "=r"(r2), "=r"(r3) : "r"(addr));
}

// ---------------- weight prepass: W[K][N] -> Wt hi/lo [n][k] bf16 -----------
__global__ __launch_bounds__(256)
void split_transpose(const float* __restrict__ W, uint32_t* __restrict__ Oh,
                     uint32_t* __restrict__ Ol, int K, int N)
{
    __shared__ float t[32][33];
    int n0 = blockIdx.x*32, k0 = blockIdx.y*32;
    int tid = threadIdx.x;
    #pragma unroll
    for (int i = 0; i < 4; i++) {
        int idx = tid + 256*i;
        int r = idx >> 5, c = idx & 31;
        t[r][c] = W[(size_t)(k0 + r)*N + n0 + c];
    }
    __syncthreads();
    #pragma unroll
    for (int i = 0; i < 2; i++) {
        int s = tid + 256*i;
        int n = s >> 4, p = s & 15;
        uint32_t h, l;
        split2(t[2*p][n], t[2*p+1][n], h, l);
        size_t off = (size_t)(n0 + n)*(K >> 1) + (k0 >> 1) + p;
        Oh[off] = h; Ol[off] = l;
    }
}

// ---------------- HMMA bf16x3 GEMM, BK=64, 3 stages, pass-split MMAs --------
#define GRS   144
#define GTILE (128*GRS)       // 18432
#define GSTG  (4*GTILE)       // 73728
#define GEMM_SMEM (3*GSTG)    // 221184

template<int ACT, int OUTP>
__global__ __launch_bounds__(256)
void hgemm(const __nv_bfloat16* __restrict__ Ah_, const __nv_bfloat16* __restrict__ Al_,
           const __nv_bfloat16* __restrict__ Bh_, const __nv_bfloat16* __restrict__ Bl_,
           const float* __restrict__ bias, const float* __restrict__ res,
           float* __restrict__ Cf, uint32_t* __restrict__ Ch, uint32_t* __restrict__ Cl,
           int M, int N, int K)
{
    extern __shared__ char smem[];
    const uint32_t sb = smem_u32(smem);
    const int tid  = threadIdx.x;
    const int wid  = tid >> 5;
    const int lane = tid & 31;
    const int bn   = blockIdx.x * 128;
    const int bm   = blockIdx.y * 128;
    const int wm   = (wid >> 2) * 64;
    const int wn   = (wid & 3) * 32;
    const int gr   = lane >> 2;
    const int cc   = lane & 3;
    const int nc   = K / 64;          // 64-col chunks

    float acc[4][4][4];
    #pragma unroll
    for (int i = 0; i < 4; i++)
        #pragma unroll
        for (int j = 0; j < 4; j++)
            #pragma unroll
            for (int r = 0; r < 4; r++) acc[i][j][r] = 0.f;

    auto load_chunk = [&](int ck, int s) {
        const uint32_t stb = sb + s*GSTG;
        const int k0 = ck * 64;
        #pragma unroll
        for (int i = 0; i < 4; i++) {
            int id = tid + 256*i;          // 0..1023
            int r = id >> 3; int c = id & 7;
            uint32_t d = stb + r*GRS + c*16;
            size_t ga = (size_t)(bm + r)*K + k0 + c*8;
            size_t gb = (size_t)(bn + r)*K + k0 + c*8;
            CP16(d,           Ah_ + ga);
            CP16(d + GTILE,   Al_ + ga);
            CP16(d + 2*GTILE, Bh_ + gb);
            CP16(d + 3*GTILE, Bl_ + gb);
        }
        CP_COMMIT();
    };

    const uint32_t aoff = (uint32_t)((wm + (lane & 15))*GRS + ((lane >> 4) & 1)*16);
    const uint32_t boff = (uint32_t)((wn + (lane & 15))*GRS + ((lane >> 4) & 1)*16);

    load_chunk(0, 0);
    if (nc > 1) load_chunk(1, 1);
    if (nc > 2) load_chunk(2, 2);

    int s = 0;
    for (int i = 0; i < nc; i++) {
        const int rem = nc - 1 - i;
        if (rem >= 2)      CP_WAIT2();
        else if (rem == 1) CP_WAIT1();
        else               CP_WAIT0();
        __syncthreads();

        const uint32_t stb = sb + s*GSTG;
        #pragma unroll
        for (int t = 0; t < 4; t++) {       // 4 k16 steps per 64-col stage
            const uint32_t ka = t*32;
            uint32_t ah[4][4], al[4][4];
            #pragma unroll
            for (int mi = 0; mi < 4; mi++) {
                ldsm4(ah[mi][0], ah[mi][1], ah[mi][2], ah[mi][3],
                      stb + aoff + mi*16*GRS + ka);
                ldsm4(al[mi][0], al[mi][1], al[mi][2], al[mi][3],
                      stb + GTILE + aoff + mi*16*GRS + ka);
            }
            uint32_t bh[4][2], bl[4][2];
            #pragma unroll
            for (int p = 0; p < 2; p++) {
                uint32_t r0, r1, r2, r3;
                ldsm4(r0, r1, r2, r3, stb + 2*GTILE + boff + p*16*GRS + ka);
                bh[2*p][0] = r0; bh[2*p][1] = r2;
                bh[2*p+1][0] = r1; bh[2*p+1][1] = r3;
                ldsm4(r0, r1, r2, r3, stb + 3*GTILE + boff + p*16*GRS + ka);
                bl[2*p][0] = r0; bl[2*p][1] = r2;
                bl[2*p+1][0] = r1; bl[2*p+1][1] = r3;
            }
            // pass-split: 16 independent MMAs per pass; per-acc order
            // hh -> hl -> lh preserved (identical FP result to triplet form).
            #pragma unroll
            for (int mi = 0; mi < 4; mi++)
                #pragma unroll
                for (int nj = 0; nj < 4; nj++)
                    mma16816(acc[mi][nj], ah[mi], bh[nj]);
            #pragma unroll
            for (int mi = 0; mi < 4; mi++)
                #pragma unroll
                for (int nj = 0; nj < 4; nj++)
                    mma16816(acc[mi][nj], ah[mi], bl[nj]);
            #pragma unroll
            for (int mi = 0; mi < 4; mi++)
                #pragma unroll
                for (int nj = 0; nj < 4; nj++)
                    mma16816(acc[mi][nj], al[mi], bh[nj]);
        }
        __syncthreads();
        if (i + 3 < nc) load_chunk(i + 3, s);
        s = (s == 2) ? 0 : s + 1;
    }

    #pragma unroll
    for (int mi = 0; mi < 4; mi++) {
        int r0 = bm + wm + mi*16 + gr;
        #pragma unroll
        for (int nj = 0; nj < 4; nj++) {
            int col = bn + wn + nj*8 + cc*2;
            float2 v0, v1;
            v0.x = acc[mi][nj][0]; v0.y = acc[mi][nj][1];
            v1.x = acc[mi][nj][2]; v1.y = acc[mi][nj][3];
            if (bias) {
                float2 bv = *(const float2*)(bias + col);
                v0.x += bv.x; v0.y += bv.y; v1.x += bv.x; v1.y += bv.y;
            }
            if (ACT == 1) {
                v0.x = gelu_f(v0.x); v0.y = gelu_f(v0.y);
                v1.x = gelu_f(v1.x); v1.y = gelu_f(v1.y);
            }
            if (res) {
                float2 ra = *(const float2*)(res + (size_t)r0*N + col);
                float2 rb = *(const float2*)(res + (size_t)(r0+8)*N + col);
                v0.x += ra.x; v0.y += ra.y; v1.x += rb.x; v1.y += rb.y;
            }
            if (OUTP == 0) {
                *(float2*)(Cf + (size_t)r0*N + col)     = v0;
                *(float2*)(Cf + (size_t)(r0+8)*N + col) = v1;
            } else {
                uint32_t hh, ll;
                split2(v0.x, v0.y, hh, ll);
                size_t p0 = ((size_t)r0*N + col) >> 1;
                Ch[p0] = hh; Cl[p0] = ll;
                split2(v1.x, v1.y, hh, ll);
                size_t p1 = ((size_t)(r0+8)*N + col) >> 1;
                Ch[p1] = hh; Cl[p1] = ll;
            }
        }
    }
}

// ---------------- LayerNorm -> bf16 hi/lo planes ----------------------------
__global__ __launch_bounds__(256)
void ln_planes(const float* __restrict__ x, const float* __restrict__ scale,
               const float* __restrict__ shift,
               uint32_t* __restrict__ yh, uint32_t* __restrict__ yl)
{
    int row = blockIdx.x;
    int tid = threadIdx.x;
    const float4* xr = (const float4*)(x + (size_t)row*EMB);
    float4 v = xr[tid];
    float s  = v.x+v.y+v.z+v.w;
    float ss = v.x*v.x+v.y*v.y+v.z*v.z+v.w*v.w;
    #pragma unroll
    for (int o = 16; o > 0; o >>= 1) {
        s  += __shfl_xor_sync(0xffffffffu, s,  o);
        ss += __shfl_xor_sync(0xffffffffu, ss, o);
    }
    __shared__ float rs[8], rss[8];
    __shared__ float s_mean, s_rstd;
    int warp = tid >> 5, lane = tid & 31;
    if (lane == 0) { rs[warp] = s; rss[warp] = ss; }
    __syncthreads();
    if (tid == 0) {
        float ts = 0.f, tss = 0.f;
        #pragma unroll
        for (int i = 0; i < 8; i++) { ts += rs[i]; tss += rss[i]; }
        float mean = ts * (1.0f/EMB);
        float var  = tss * (1.0f/EMB) - mean*mean;
        s_mean = mean;
        s_rstd = rsqrtf(var + 1e-5f);
    }
    __syncthreads();
    float mean = s_mean, rstd = s_rstd;
    float4 sc = ((const float4*)scale)[tid];
    float4 sh = ((const float4*)shift)[tid];
    float o0 = sc.x*(v.x-mean)*rstd + sh.x;
    float o1 = sc.y*(v.y-mean)*rstd + sh.y;
    float o2 = sc.z*(v.z-mean)*rstd + sh.z;
    float o3 = sc.w*(v.w-mean)*rstd + sh.w;
    uint32_t h0, l0, h1, l1;
    split2(o0, o1, h0, l0);
    split2(o2, o3, h1, l1);
    size_t p = (size_t)row*(EMB/2) + tid*2;
    uint2 hv; hv.x = h0; hv.y = h1;
    uint2 lv; lv.x = l0; lv.y = l1;
    *(uint2*)(yh + p) = hv;
    *(uint2*)(yl + p) = lv;
}

// ---------------- Tensor-core flash attention (R9 config) -------------------
#define ARS   144
#define ATILE (64*ARS)      // 9216
#define ASTG  (4*ATILE)     // 36864
#define ATTN_SMEM (2*ASTG)  // 73728

__global__ __launch_bounds__(128)
void attn_mma(const __nv_bfloat16* __restrict__ Ph, const __nv_bfloat16* __restrict__ Pl,
              uint32_t* __restrict__ Oh, uint32_t* __restrict__ Ol)
{
    extern __shared__ char smem[];
    const uint32_t sb = smem_u32(smem);
    const int qt  = blockIdx.x;
    const int hd  = blockIdx.y;
    const int b   = blockIdx.z;
    const int tid = threadIdx.x;
    const int wid = tid >> 5, lane = tid & 31;
    const int gr  = lane >> 2, cc = lane & 3;
    const int nt  = qt + 1;
    const size_t tokbase = (size_t)b * SEQ;
    const int colq = hd * HD;

    #pragma unroll
    for (int i = 0; i < 4; i++) {
        int id = tid + 128*i; int r = id >> 3; int c = id & 7;
        size_t g = (tokbase + qt*64 + r)*QKS + colq + c*8;
        CP16(sb + r*ARS + c*16,         Ph + g);
        CP16(sb + ATILE + r*ARS + c*16, Pl + g);
    }
    CP_COMMIT(); CP_WAIT0();
    __syncthreads();

    uint32_t qfh[4][4], qfl[4][4];
    {
        const uint32_t qoff = (uint32_t)((wid*16 + (lane & 15))*ARS + ((lane >> 4) & 1)*16);
        #pragma unroll
        for (int t = 0; t < 4; t++) {
            ldsm4(qfh[t][0], qfh[t][1], qfh[t][2], qfh[t][3], sb + qoff + t*32);
            ldsm4(qfl[t][0], qfl[t][1], qfl[t][2], qfl[t][3], sb + ATILE + qoff + t*32);
        }
    }
    __syncthreads();

    float oacc[8][4];
    #pragma unroll
    for (int j = 0; j < 8; j++)
        #pragma unroll
        for (int r = 0; r < 4; r++) oacc[j][r] = 0.f;
    float m0 = -INFINITY, m1 = -INFINITY, l0 = 0.f, l1 = 0.f;

    auto load_kv = [&](int kb, int s) {
        const uint32_t base = sb + s*ASTG;
        #pragma unroll
        for (int i = 0; i < 4; i++) {
            int id = tid + 128*i; int r = id >> 3; int c = id & 7;
            size_t g = (tokbase + kb*64 + r)*QKS + colq + c*8;
            CP16(base           + r*ARS + c*16, Ph + g + 1024);   // K hi
            CP16(base + ATILE   + r*ARS + c*16, Pl + g + 1024);   // K lo
            CP16(base + 2*ATILE + r*ARS + c*16, Ph + g + 2048);   // V hi
            CP16(base + 3*ATILE + r*ARS + c*16, Pl + g + 2048);   // V lo
        }
        CP_COMMIT();
    };

    load_kv(0, 0);
    if (nt > 1) load_kv(1, 1);

    const uint32_t koff = (uint32_t)(((lane & 15))*ARS + ((lane >> 4) & 1)*16);
    const int rowg0 = qt*64 + wid*16 + gr;
    const int rowg1 = rowg0 + 8;

    for (int kb = 0; kb < nt; kb++) {
        const int s = kb & 1;
        if (kb + 1 < nt) CP_WAIT1(); else CP_WAIT0();
        __syncthreads();
        const uint32_t kbase = sb + s*ASTG;

        float sacc[8][4];
        #pragma unroll
        for (int j = 0; j < 8; j++)
            #pragma unroll
            for (int r = 0; r < 4; r++) sacc[j][r] = 0.f;

        #pragma unroll
        for (int t = 0; t < 4; t++) {
            uint32_t bh[8][2], bl[8][2];
            #pragma unroll
            for (int p = 0; p < 4; p++) {
                uint32_t a = kbase + p*16*ARS + koff + t*32;
                uint32_t r0, r1, r2, r3;
                ldsm4(r0, r1, r2, r3, a);
                bh[2*p][0] = r0; bh[2*p][1] = r2;
                bh[2*p+1][0] = r1; bh[2*p+1][1] = r3;
                ldsm4(r0, r1, r2, r3, a + ATILE);
                bl[2*p][0] = r0; bl[2*p][1] = r2;
                bl[2*p+1][0] = r1; bl[2*p+1][1] = r3;
            }
            #pragma unroll
            for (int j = 0; j < 8; j++) {
                mma16816(sacc[j], qfh[t], bh[j]);
                mma16816(sacc[j], qfh[t], bl[j]);
                mma16816(sacc[j], qfl[t], bh[j]);
            }
        }

        const bool diag = (kb == qt);
        float rmax0 = -INFINITY, rmax1 = -INFINITY;
        #pragma unroll
        for (int j = 0; j < 8; j++) {
            int c0 = kb*64 + j*8 + cc*2;
            float v0 = sacc[j][0]*0.125f, v1 = sacc[j][1]*0.125f;
            float v2 = sacc[j][2]*0.125f, v3 = sacc[j][3]*0.125f;
            if (diag) {
                if (c0     > rowg0) v0 = -INFINITY;
                if (c0 + 1 > rowg0) v1 = -INFINITY;
                if (c0     > rowg1) v2 = -INFINITY;
                if (c0 + 1 > rowg1) v3 = -INFINITY;
            }
            sacc[j][0] = v0; sacc[j][1] = v1; sacc[j][2] = v2; sacc[j][3] = v3;
            rmax0 = fmaxf(rmax0, fmaxf(v0, v1));
            rmax1 = fmaxf(rmax1, fmaxf(v2, v3));
        }
        rmax0 = fmaxf(rmax0, __shfl_xor_sync(0xffffffffu, rmax0, 1));
        rmax0 = fmaxf(rmax0, __shfl_xor_sync(0xffffffffu, rmax0, 2));
        rmax1 = fmaxf(rmax1, __shfl_xor_sync(0xffffffffu, rmax1, 1));
        rmax1 = fmaxf(rmax1, __shfl_xor_sync(0xffffffffu, rmax1, 2));
        float mn0 = fmaxf(m0, rmax0), mn1 = fmaxf(m1, rmax1);
        float cor0 = __expf(m0 - mn0), cor1 = __expf(m1 - mn1);
        m0 = mn0; m1 = mn1;
        float rs0 = 0.f, rs1 = 0.f;
        #pragma unroll
        for (int j = 0; j < 8; j++) {
            float p0 = __expf(sacc[j][0] - mn0);
            float p1 = __expf(sacc[j][1] - mn0);
            float p2 = __expf(sacc[j][2] - mn1);
            float p3 = __expf(sacc[j][3] - mn1);
            sacc[j][0] = p0; sacc[j][1] = p1; sacc[j][2] = p2; sacc[j][3] = p3;
            rs0 += p0 + p1; rs1 += p2 + p3;
        }
        rs0 += __shfl_xor_sync(0xffffffffu, rs0, 1);
        rs0 += __shfl_xor_sync(0xffffffffu, rs0, 2);
        rs1 += __shfl_xor_sync(0xffffffffu, rs1, 1);
        rs1 += __shfl_xor_sync(0xffffffffu, rs1, 2);
        l0 = l0*cor0 + rs0;
        l1 = l1*cor1 + rs1;
        #pragma unroll
        for (int j = 0; j < 8; j++) {
            oacc[j][0] *= cor0; oacc[j][1] *= cor0;
            oacc[j][2] *= cor1; oacc[j][3] *= cor1;
        }

        #pragma unroll
        for (int t = 0; t < 4; t++) {
            uint32_t pah[4], pal[4];
            split2(sacc[2*t][0],   sacc[2*t][1],   pah[0], pal[0]);
            split2(sacc[2*t][2],   sacc[2*t][3],   pah[1], pal[1]);
            split2(sacc[2*t+1][0], sacc[2*t+1][1], pah[2], pal[2]);
            split2(sacc[2*t+1][2], sacc[2*t+1][3], pah[3], pal[3]);
            uint32_t vh[8][2], vl[8][2];
            #pragma unroll
            for (int u = 0; u < 4; u++) {
                uint32_t a = kbase + 2*ATILE + (16*t + (lane & 15))*ARS
                           + u*32 + ((lane >> 4) & 1)*16;
                uint32_t r0, r1, r2, r3;
                ldsm4t(r0, r1, r2, r3, a);
                vh[2*u][0] = r0; vh[2*u][1] = r1;
                vh[2*u+1][0] = r2; vh[2*u+1][1] = r3;
                ldsm4t(r0, r1, r2, r3, a + ATILE);
                vl[2*u][0] = r0; vl[2*u][1] = r1;
                vl[2*u+1][0] = r2; vl[2*u+1][1] = r3;
            }
            #pragma unroll
            for (int j = 0; j < 8; j++) {
                mma16816(oacc[j], pah, vh[j]);
                mma16816(oacc[j], pah, vl[j]);
                mma16816(oacc[j], pal, vh[j]);
            }
        }
        __syncthreads();
        if (kb + 2 < nt) load_kv(kb + 2, s);
    }

    const float inv0 = 1.0f / l0, inv1 = 1.0f / l1;
    const size_t tok0 = tokbase + qt*64 + wid*16 + gr;
    #pragma unroll
    for (int j = 0; j < 8; j++) {
        int col = colq + j*8 + cc*2;
        uint32_t hh, ll;
        split2(oacc[j][0]*inv0, oacc[j][1]*inv0, hh, ll);
        size_t p0 = (tok0*EMB + col) >> 1;
        Oh[p0] = hh; Ol[p0] = ll;
        split2(oacc[j][2]*inv1, oacc[j][3]*inv1, hh, ll);
        size_t p1 = ((tok0 + 8)*EMB + col) >> 1;
        Oh[p1] = hh; Ol[p1] = ll;
    }
}

// ---------------- launch -----------------------------------------------------
extern "C" void kernel_launch(void* const* d_in, const int* in_sizes, int n_in,
                              void* d_out, int out_size)
{
    const float* x      = (const float*)d_in[0];
    const float* ln1_s  = (const float*)d_in[1];
    const float* ln1_b  = (const float*)d_in[2];
    const float* Wq     = (const float*)d_in[3];
    const float* Wk     = (const float*)d_in[4];
    const float* Wv     = (const float*)d_in[5];
    const float* Wo     = (const float*)d_in[6];
    const float* bo     = (const float*)d_in[7];
    const float* ln2_s  = (const float*)d_in[8];
    const float* ln2_b  = (const float*)d_in[9];
    const float* W1     = (const float*)d_in[10];
    const float* b1     = (const float*)d_in[11];
    const float* W2     = (const float*)d_in[12];
    const float* b2     = (const float*)d_in[13];
    float* out = (float*)d_out;

    void* parena = nullptr;
    cudaGetSymbolAddress(&parena, g_arena);
    float* arena = (float*)parena;

    uint32_t* qkvh = (uint32_t*)arena;
    uint32_t* qkvl = (uint32_t*)(arena + (size_t)MTOK*1536);
    float* x1  = arena + OF_X1;
    uint32_t* h_hi   = (uint32_t*)(arena + OF_HB + HSLOT*0);
    uint32_t* h_lo   = (uint32_t*)(arena + OF_HB + HSLOT*1);
    uint32_t* h2_hi  = (uint32_t*)(arena + OF_HB + HSLOT*2);
    uint32_t* h2_lo  = (uint32_t*)(arena + OF_HB + HSLOT*3);
    uint32_t* ctx_hi = (uint32_t*)(arena + OF_HB + HSLOT*4);
    uint32_t* ctx_lo = (uint32_t*)(arena + OF_HB + HSLOT*5);
    uint32_t* ffn_hi = (uint32_t*)(arena + OF_FFN);
    uint32_t* ffn_lo = (uint32_t*)(arena + OF_FFN + FSLOT);

    uint32_t* wb   = (uint32_t*)(arena + OF_WT);
    uint32_t* wqvh = wb;                  uint32_t* wqvl = wqvh + PLANE_Q;
    uint32_t* woh  = wqvl + PLANE_Q;      uint32_t* wol  = woh  + PLANE_E;
    uint32_t* w1h  = wol  + PLANE_E;      uint32_t* w1l  = w1h  + PLANE_F;
    uint32_t* w2h  = w1l  + PLANE_F;      uint32_t* w2l  = w2h  + PLANE_F;

    cudaFuncSetAttribute(hgemm<0,0>, cudaFuncAttributeMaxDynamicSharedMemorySize, GEMM_SMEM);
    cudaFuncSetAttribute(hgemm<0,1>, cudaFuncAttributeMaxDynamicSharedMemorySize, GEMM_SMEM);
    cudaFuncSetAttribute(hgemm<1,1>, cudaFuncAttributeMaxDynamicSharedMemorySize, GEMM_SMEM);
    cudaFuncSetAttribute(attn_mma,   cudaFuncAttributeMaxDynamicSharedMemorySize, ATTN_SMEM);

    dim3 pE(EMB/32, EMB/32);
    dim3 gQ(QKS/128, MTOK/128);
    dim3 gE(EMB/128, MTOK/128);
    dim3 gF(FF/128,  MTOK/128);

    // weight prepass (qkv + wo)
    split_transpose<<<pE, 256>>>(Wq, wqvh,            wqvl,            EMB, EMB);
    split_transpose<<<pE, 256>>>(Wk, wqvh + 1024*512, wqvl + 1024*512, EMB, EMB);
    split_transpose<<<pE, 256>>>(Wv, wqvh + 2048*512, wqvl + 2048*512, EMB, EMB);
    split_transpose<<<pE, 256>>>(Wo, woh, wol, EMB, EMB);
    // LN1 -> h planes
    ln_planes<<<MTOK, 256>>>(x, ln1_s, ln1_b, h_hi, h_lo);
    // fused QKV projection -> bf16 planes
    hgemm<0,1><<<gQ, 256, GEMM_SMEM>>>((__nv_bfloat16*)h_hi, (__nv_bfloat16*)h_lo,
        (__nv_bfloat16*)wqvh, (__nv_bfloat16*)wqvl, nullptr, nullptr, nullptr, qkvh, qkvl,
        MTOK, QKS, EMB);
    // tensor-core causal flash attention -> ctx planes
    attn_mma<<<dim3(SEQ/64, HEADS, BATCH), 128, ATTN_SMEM>>>(
        (const __nv_bfloat16*)qkvh, (const __nv_bfloat16*)qkvl, ctx_hi, ctx_lo);
    // x1 = x + ctx@Wo + bo
    hgemm<0,0><<<gE, 256, GEMM_SMEM>>>((__nv_bfloat16*)ctx_hi, (__nv_bfloat16*)ctx_lo,
        (__nv_bfloat16*)woh, (__nv_bfloat16*)wol, bo, x, x1, nullptr, nullptr,
        MTOK, EMB, EMB);
    // LN2 -> h2 planes
    ln_planes<<<MTOK, 256>>>(x1, ln2_s, ln2_b, h2_hi, h2_lo);
    // W1 prepass
    split_transpose<<<dim3(FF/32,  EMB/32), 256>>>(W1, w1h, w1l, EMB, FF);
    // FFN up + GELU -> ffn planes
    hgemm<1,1><<<gF, 256, GEMM_SMEM>>>((__nv_bfloat16*)h2_hi, (__nv_bfloat16*)h2_lo,
        (__nv_bfloat16*)w1h, (__nv_bfloat16*)w1l, b1, nullptr, nullptr, ffn_hi, ffn_lo,
        MTOK, FF, EMB);
    // W2 prepass
    split_transpose<<<dim3(EMB/32, FF/32 ), 256>>>(W2, w2h, w2l, FF, EMB);
    // out = x1 + ffn@W2 + b2
    hgemm<0,0><<<gE, 256, GEMM_SMEM>>>((__nv_bfloat16*)ffn_hi, (__nv_bfloat16*)ffn_lo,
        (__nv_bfloat16*)w2h, (__nv_bfloat16*)w2l, b2, x1, out, nullptr, nullptr,
        MTOK, EMB, FF);
}

// round 14
// speedup vs baseline: 1.0170x; 1.0170x over previous
#include <cuda_runtime.h>
#include <cuda_bf16.h>
#include <math.h>
#include <stdint.h>

#define EMB   1024
#define SEQ   2048
#define BATCH 2
#define MTOK  (BATCH*SEQ)   // 4096
#define FF    4096
#define HEADS 16
#define HD    64
#define QKS   3072          // fused qkv col count

// ---------------- arena ------------------------------------------------------
#define SLOT    ((size_t)MTOK*EMB)
#define HSLOT   (SLOT/2)
#define FSLOT   ((size_t)MTOK*FF/2)
#define PLANE_Q 1572864ull
#define PLANE_E 524288ull
#define PLANE_F 2097152ull
#define OF_X1   (SLOT*3)
#define OF_HB   (SLOT*4)
#define OF_FFN  (OF_HB + HSLOT*6)
#define OF_WT   (OF_FFN + FSLOT*2)
__device__ float g_arena[OF_WT + 2ull*PLANE_Q + 2ull*PLANE_E + 4ull*PLANE_F];

// ---------------- helpers ----------------------------------------------------
__device__ __forceinline__ void split2(float x0, float x1, uint32_t& hi, uint32_t& lo)
{
    __nv_bfloat16 h0 = __float2bfloat16(x0);
    __nv_bfloat16 h1 = __float2bfloat16(x1);
    __nv_bfloat16 l0 = __float2bfloat16(x0 - __bfloat162float(h0));
    __nv_bfloat16 l1 = __float2bfloat16(x1 - __bfloat162float(h1));
    hi = (uint32_t)__bfloat16_as_ushort(h0) | ((uint32_t)__bfloat16_as_ushort(h1) << 16);
    lo = (uint32_t)__bfloat16_as_ushort(l0) | ((uint32_t)__bfloat16_as_ushort(l1) << 16);
}

__device__ __forceinline__ float gelu_f(float x)
{
    float x3 = x*x*x;
    float t  = tanhf(0.7978845608028654f*(x + 0.044715f*x3));
    return 0.5f*x*(1.0f + t);
}

__device__ __forceinline__ uint32_t smem_u32(const void* p)
{
    return (uint32_t)__cvta_generic_to_shared(p);
}

#define CP16(dst, src) \
    asm volatile("cp.async.cg.shared.global [%0], [%1], 16;\n" :: "r"(dst), "l"(src))
#define CP_COMMIT() asm volatile("cp.async.commit_group;\n" ::: "memory")
#define CP_WAIT0()  asm volatile("cp.async.wait_group 0;\n" ::: "memory")
#define CP_WAIT1()  asm volatile("cp.async.wait_group 1;\n" ::: "memory")

__device__ __forceinline__ void mma16816(float* c, const uint32_t* a, const uint32_t* b)
{
    asm volatile(
        "mma.sync.aligned.m16n8k16.row.col.f32.bf16.bf16.f32 "
        "{%0,%1,%2,%3},{%4,%5,%6,%7},{%8,%9},{%0,%1,%2,%3};"
        : "+f"(c[0]), "+f"(c[1]), "+f"(c[2]), "+f"(c[3])
        : "r"(a[0]), "r"(a[1]), "r"(a[2]), "r"(a[3]), "r"(b[0]), "r"(b[1]));
}

__device__ __forceinline__ void ldsm4(uint32_t& r0, uint32_t& r1, uint32_t& r2,
                                      uint32_t& r3, uint32_t addr)
{
    asm volatile("ldmatrix.sync.aligned.m8n8.x4.shared.b16 {%0,%1,%2,%3}, [%4];"
        : "=r"(r0), "=r"(r1), "=r"(r2), "=r"(r3) : "r"(addr));
}

__device__ __forceinline__ void ldsm4t(uint32_t& r0, uint32_t& r1, uint32_t& r2,
                                       uint32_t& r3, uint32_t addr)
{
    asm volatile("ldmatrix.sync.aligned.m8n8.x4.trans.shared.b16 {%0,%1,%2,%3}, [%4];"
        : "=r"(r0), "=r"(r1), "=r"(r2), "=r"(r3) : "r"(addr));
}

// ---------------- weight prepass: W[K][N] -> Wt hi/lo [n][k] bf16 -----------
__global__ __launch_bounds__(256)
void split_transpose(const float* __restrict__ W, uint32_t* __restrict__ Oh,
                     uint32_t* __restrict__ Ol, int K, int N)
{
    __shared__ float t[32][33];
    int n0 = blockIdx.x*32, k0 = blockIdx.y*32;
    int tid = threadIdx.x;
    #pragma unroll
    for (int i = 0; i < 4; i++) {
        int idx = tid + 256*i;
        int r = idx >> 5, c = idx & 31;
        t[r][c] = W[(size_t)(k0 + r)*N + n0 + c];
    }
    __syncthreads();
    #pragma unroll
    for (int i = 0; i < 2; i++) {
        int s = tid + 256*i;
        int n = s >> 4, p = s & 15;
        uint32_t h, l;
        split2(t[2*p][n], t[2*p+1][n], h, l);
        size_t off = (size_t)(n0 + n)*(K >> 1) + (k0 >> 1) + p;
        Oh[off] = h; Ol[off] = l;
    }
}

// ---------------- HMMA bf16x3 GEMM: 128x256 CTA tile, 64x64 warp tile -------
// Stage: AH(128r) AL(128r) BH(256r) BL(256r) @ 144B stride. 2 stages.
#define GRS   144
#define ATB   (128*GRS)       // 18432 (A plane)
#define BTB   (256*GRS)       // 36864 (B plane)
#define GSTG  (2*ATB + 2*BTB) // 110592
#define OFF_BH (2*ATB)        // 36864
#define GEMM_SMEM (2*GSTG)    // 221184

template<int ACT, int OUTP>
__global__ __launch_bounds__(256)
void hgemm(const __nv_bfloat16* __restrict__ Ah_, const __nv_bfloat16* __restrict__ Al_,
           const __nv_bfloat16* __restrict__ Bh_, const __nv_bfloat16* __restrict__ Bl_,
           const float* __restrict__ bias, const float* __restrict__ res,
           float* __restrict__ Cf, uint32_t* __restrict__ Ch, uint32_t* __restrict__ Cl,
           int M, int N, int K)
{
    extern __shared__ char smem[];
    const uint32_t sb = smem_u32(smem);
    const int tid  = threadIdx.x;
    const int wid  = tid >> 5;
    const int lane = tid & 31;
    const int bn   = blockIdx.x * 256;
    const int bm   = blockIdx.y * 128;
    const int wm   = (wid >> 2) * 64;      // 0 or 64
    const int wn   = (wid & 3) * 64;       // 0,64,128,192
    const int gr   = lane >> 2;
    const int cc   = lane & 3;
    const int nc   = K / 64;

    float acc[4][8][4];
    #pragma unroll
    for (int i = 0; i < 4; i++)
        #pragma unroll
        for (int j = 0; j < 8; j++)
            #pragma unroll
            for (int r = 0; r < 4; r++) acc[i][j][r] = 0.f;

    auto load_chunk = [&](int ck, int s) {
        const uint32_t stb = sb + s*GSTG;
        const int k0 = ck * 64;
        #pragma unroll
        for (int i = 0; i < 4; i++) {              // A: 128 rows, both planes
            int id = tid + 256*i;
            int r = id >> 3; int c = id & 7;
            uint32_t d = stb + r*GRS + c*16;
            size_t ga = (size_t)(bm + r)*K + k0 + c*8;
            CP16(d,       Ah_ + ga);
            CP16(d + ATB, Al_ + ga);
        }
        #pragma unroll
        for (int i = 0; i < 8; i++) {              // B: 256 rows, both planes
            int id = tid + 256*i;
            int r = id >> 3; int c = id & 7;
            uint32_t d = stb + OFF_BH + r*GRS + c*16;
            size_t gb = (size_t)(bn + r)*K + k0 + c*8;
            CP16(d,       Bh_ + gb);
            CP16(d + BTB, Bl_ + gb);
        }
        CP_COMMIT();
    };

    const uint32_t aoff = (uint32_t)((wm + (lane & 15))*GRS + ((lane >> 4) & 1)*16);
    const uint32_t boff = (uint32_t)((wn + (lane & 15))*GRS + ((lane >> 4) & 1)*16);

    load_chunk(0, 0);
    if (nc > 1) load_chunk(1, 1);

    for (int i = 0; i < nc; i++) {
        const int s = i & 1;
        if (i + 1 < nc) CP_WAIT1(); else CP_WAIT0();
        __syncthreads();

        const uint32_t stb = sb + s*GSTG;
        #pragma unroll
        for (int t = 0; t < 4; t++) {
            const uint32_t ka = t*32;
            uint32_t ah[4][4], al[4][4];
            #pragma unroll
            for (int mi = 0; mi < 4; mi++) {
                ldsm4(ah[mi][0], ah[mi][1], ah[mi][2], ah[mi][3],
                      stb + aoff + mi*16*GRS + ka);
                ldsm4(al[mi][0], al[mi][1], al[mi][2], al[mi][3],
                      stb + ATB + aoff + mi*16*GRS + ka);
            }
            #pragma unroll
            for (int h = 0; h < 2; h++) {          // two n-halves of 32 cols
                uint32_t bh[4][2], bl[4][2];
                #pragma unroll
                for (int p = 0; p < 2; p++) {
                    uint32_t a = stb + OFF_BH + boff + (h*32 + p*16)*GRS + ka;
                    uint32_t r0, r1, r2, r3;
                    ldsm4(r0, r1, r2, r3, a);
                    bh[2*p][0] = r0; bh[2*p][1] = r2;
                    bh[2*p+1][0] = r1; bh[2*p+1][1] = r3;
                    ldsm4(r0, r1, r2, r3, a + BTB);
                    bl[2*p][0] = r0; bl[2*p][1] = r2;
                    bl[2*p+1][0] = r1; bl[2*p+1][1] = r3;
                }
                #pragma unroll
                for (int mi = 0; mi < 4; mi++)
                    #pragma unroll
                    for (int nj = 0; nj < 4; nj++) {
                        float* a4 = acc[mi][h*4 + nj];
                        mma16816(a4, ah[mi], bh[nj]);
                        mma16816(a4, ah[mi], bl[nj]);
                        mma16816(a4, al[mi], bh[nj]);
                    }
            }
        }
        __syncthreads();
        if (i + 2 < nc) load_chunk(i + 2, s);
    }

    #pragma unroll
    for (int mi = 0; mi < 4; mi++) {
        int r0 = bm + wm + mi*16 + gr;
        #pragma unroll
        for (int nj = 0; nj < 8; nj++) {
            int col = bn + wn + nj*8 + cc*2;
            float2 v0, v1;
            v0.x = acc[mi][nj][0]; v0.y = acc[mi][nj][1];
            v1.x = acc[mi][nj][2]; v1.y = acc[mi][nj][3];
            if (bias) {
                float2 bv = *(const float2*)(bias + col);
                v0.x += bv.x; v0.y += bv.y; v1.x += bv.x; v1.y += bv.y;
            }
            if (ACT == 1) {
                v0.x = gelu_f(v0.x); v0.y = gelu_f(v0.y);
                v1.x = gelu_f(v1.x); v1.y = gelu_f(v1.y);
            }
            if (res) {
                float2 ra = *(const float2*)(res + (size_t)r0*N + col);
                float2 rb = *(const float2*)(res + (size_t)(r0+8)*N + col);
                v0.x += ra.x; v0.y += ra.y; v1.x += rb.x; v1.y += rb.y;
            }
            if (OUTP == 0) {
                *(float2*)(Cf + (size_t)r0*N + col)     = v0;
                *(float2*)(Cf + (size_t)(r0+8)*N + col) = v1;
            } else {
                uint32_t hh, ll;
                split2(v0.x, v0.y, hh, ll);
                size_t p0 = ((size_t)r0*N + col) >> 1;
                Ch[p0] = hh; Cl[p0] = ll;
                split2(v1.x, v1.y, hh, ll);
                size_t p1 = ((size_t)(r0+8)*N + col) >> 1;
                Ch[p1] = hh; Cl[p1] = ll;
            }
        }
    }
}

// ---------------- LayerNorm -> bf16 hi/lo planes ----------------------------
__global__ __launch_bounds__(256)
void ln_planes(const float* __restrict__ x, const float* __restrict__ scale,
               const float* __restrict__ shift,
               uint32_t* __restrict__ yh, uint32_t* __restrict__ yl)
{
    int row = blockIdx.x;
    int tid = threadIdx.x;
    const float4* xr = (const float4*)(x + (size_t)row*EMB);
    float4 v = xr[tid];
    float s  = v.x+v.y+v.z+v.w;
    float ss = v.x*v.x+v.y*v.y+v.z*v.z+v.w*v.w;
    #pragma unroll
    for (int o = 16; o > 0; o >>= 1) {
        s  += __shfl_xor_sync(0xffffffffu, s,  o);
        ss += __shfl_xor_sync(0xffffffffu, ss, o);
    }
    __shared__ float rs[8], rss[8];
    __shared__ float s_mean, s_rstd;
    int warp = tid >> 5, lane = tid & 31;
    if (lane == 0) { rs[warp] = s; rss[warp] = ss; }
    __syncthreads();
    if (tid == 0) {
        float ts = 0.f, tss = 0.f;
        #pragma unroll
        for (int i = 0; i < 8; i++) { ts += rs[i]; tss += rss[i]; }
        float mean = ts * (1.0f/EMB);
        float var  = tss * (1.0f/EMB) - mean*mean;
        s_mean = mean;
        s_rstd = rsqrtf(var + 1e-5f);
    }
    __syncthreads();
    float mean = s_mean, rstd = s_rstd;
    float4 sc = ((const float4*)scale)[tid];
    float4 sh = ((const float4*)shift)[tid];
    float o0 = sc.x*(v.x-mean)*rstd + sh.x;
    float o1 = sc.y*(v.y-mean)*rstd + sh.y;
    float o2 = sc.z*(v.z-mean)*rstd + sh.z;
    float o3 = sc.w*(v.w-mean)*rstd + sh.w;
    uint32_t h0, l0, h1, l1;
    split2(o0, o1, h0, l0);
    split2(o2, o3, h1, l1);
    size_t p = (size_t)row*(EMB/2) + tid*2;
    uint2 hv; hv.x = h0; hv.y = h1;
    uint2 lv; lv.x = l0; lv.y = l1;
    *(uint2*)(yh + p) = hv;
    *(uint2*)(yl + p) = lv;
}

// ---------------- Tensor-core flash attention (R9 config) -------------------
#define ARS   144
#define ATILE (64*ARS)      // 9216
#define ASTG  (4*ATILE)     // 36864
#define ATTN_SMEM (2*ASTG)  // 73728

__global__ __launch_bounds__(128)
void attn_mma(const __nv_bfloat16* __restrict__ Ph, const __nv_bfloat16* __restrict__ Pl,
              uint32_t* __restrict__ Oh, uint32_t* __restrict__ Ol)
{
    extern __shared__ char smem[];
    const uint32_t sb = smem_u32(smem);
    const int qt  = blockIdx.x;
    const int hd  = blockIdx.y;
    const int b   = blockIdx.z;
    const int tid = threadIdx.x;
    const int wid = tid >> 5, lane = tid & 31;
    const int gr  = lane >> 2, cc = lane & 3;
    const int nt  = qt + 1;
    const size_t tokbase = (size_t)b * SEQ;
    const int colq = hd * HD;

    #pragma unroll
    for (int i = 0; i < 4; i++) {
        int id = tid + 128*i; int r = id >> 3; int c = id & 7;
        size_t g = (tokbase + qt*64 + r)*QKS + colq + c*8;
        CP16(sb + r*ARS + c*16,         Ph + g);
        CP16(sb + ATILE + r*ARS + c*16, Pl + g);
    }
    CP_COMMIT(); CP_WAIT0();
    __syncthreads();

    uint32_t qfh[4][4], qfl[4][4];
    {
        const uint32_t qoff = (uint32_t)((wid*16 + (lane & 15))*ARS + ((lane >> 4) & 1)*16);
        #pragma unroll
        for (int t = 0; t < 4; t++) {
            ldsm4(qfh[t][0], qfh[t][1], qfh[t][2], qfh[t][3], sb + qoff + t*32);
            ldsm4(qfl[t][0], qfl[t][1], qfl[t][2], qfl[t][3], sb + ATILE + qoff + t*32);
        }
    }
    __syncthreads();

    float oacc[8][4];
    #pragma unroll
    for (int j = 0; j < 8; j++)
        #pragma unroll
        for (int r = 0; r < 4; r++) oacc[j][r] = 0.f;
    float m0 = -INFINITY, m1 = -INFINITY, l0 = 0.f, l1 = 0.f;

    auto load_kv = [&](int kb, int s) {
        const uint32_t base = sb + s*ASTG;
        #pragma unroll
        for (int i = 0; i < 4; i++) {
            int id = tid + 128*i; int r = id >> 3; int c = id & 7;
            size_t g = (tokbase + kb*64 + r)*QKS + colq + c*8;
            CP16(base           + r*ARS + c*16, Ph + g + 1024);   // K hi
            CP16(base + ATILE   + r*ARS + c*16, Pl + g + 1024);   // K lo
            CP16(base + 2*ATILE + r*ARS + c*16, Ph + g + 2048);   // V hi
            CP16(base + 3*ATILE + r*ARS + c*16, Pl + g + 2048);   // V lo
        }
        CP_COMMIT();
    };

    load_kv(0, 0);
    if (nt > 1) load_kv(1, 1);

    const uint32_t koff = (uint32_t)(((lane & 15))*ARS + ((lane >> 4) & 1)*16);
    const int rowg0 = qt*64 + wid*16 + gr;
    const int rowg1 = rowg0 + 8;

    for (int kb = 0; kb < nt; kb++) {
        const int s = kb & 1;
        if (kb + 1 < nt) CP_WAIT1(); else CP_WAIT0();
        __syncthreads();
        const uint32_t kbase = sb + s*ASTG;

        float sacc[8][4];
        #pragma unroll
        for (int j = 0; j < 8; j++)
            #pragma unroll
            for (int r = 0; r < 4; r++) sacc[j][r] = 0.f;

        #pragma unroll
        for (int t = 0; t < 4; t++) {
            uint32_t bh[8][2], bl[8][2];
            #pragma unroll
            for (int p = 0; p < 4; p++) {
                uint32_t a = kbase + p*16*ARS + koff + t*32;
                uint32_t r0, r1, r2, r3;
                ldsm4(r0, r1, r2, r3, a);
                bh[2*p][0] = r0; bh[2*p][1] = r2;
                bh[2*p+1][0] = r1; bh[2*p+1][1] = r3;
                ldsm4(r0, r1, r2, r3, a + ATILE);
                bl[2*p][0] = r0; bl[2*p][1] = r2;
                bl[2*p+1][0] = r1; bl[2*p+1][1] = r3;
            }
            #pragma unroll
            for (int j = 0; j < 8; j++) {
                mma16816(sacc[j], qfh[t], bh[j]);
                mma16816(sacc[j], qfh[t], bl[j]);
                mma16816(sacc[j], qfl[t], bh[j]);
            }
        }

        const bool diag = (kb == qt);
        float rmax0 = -INFINITY, rmax1 = -INFINITY;
        #pragma unroll
        for (int j = 0; j < 8; j++) {
            int c0 = kb*64 + j*8 + cc*2;
            float v0 = sacc[j][0]*0.125f, v1 = sacc[j][1]*0.125f;
            float v2 = sacc[j][2]*0.125f, v3 = sacc[j][3]*0.125f;
            if (diag) {
                if (c0     > rowg0) v0 = -INFINITY;
                if (c0 + 1 > rowg0) v1 = -INFINITY;
                if (c0     > rowg1) v2 = -INFINITY;
                if (c0 + 1 > rowg1) v3 = -INFINITY;
            }
            sacc[j][0] = v0; sacc[j][1] = v1; sacc[j][2] = v2; sacc[j][3] = v3;
            rmax0 = fmaxf(rmax0, fmaxf(v0, v1));
            rmax1 = fmaxf(rmax1, fmaxf(v2, v3));
        }
        rmax0 = fmaxf(rmax0, __shfl_xor_sync(0xffffffffu, rmax0, 1));
        rmax0 = fmaxf(rmax0, __shfl_xor_sync(0xffffffffu, rmax0, 2));
        rmax1 = fmaxf(rmax1, __shfl_xor_sync(0xffffffffu, rmax1, 1));
        rmax1 = fmaxf(rmax1, __shfl_xor_sync(0xffffffffu, rmax1, 2));
        float mn0 = fmaxf(m0, rmax0), mn1 = fmaxf(m1, rmax1);
        float cor0 = __expf(m0 - mn0), cor1 = __expf(m1 - mn1);
        m0 = mn0; m1 = mn1;
        float rs0 = 0.f, rs1 = 0.f;
        #pragma unroll
        for (int j = 0; j < 8; j++) {
            float p0 = __expf(sacc[j][0] - mn0);
            float p1 = __expf(sacc[j][1] - mn0);
            float p2 = __expf(sacc[j][2] - mn1);
            float p3 = __expf(sacc[j][3] - mn1);
            sacc[j][0] = p0; sacc[j][1] = p1; sacc[j][2] = p2; sacc[j][3] = p3;
            rs0 += p0 + p1; rs1 += p2 + p3;
        }
        rs0 += __shfl_xor_sync(0xffffffffu, rs0, 1);
        rs0 += __shfl_xor_sync(0xffffffffu, rs0, 2);
        rs1 += __shfl_xor_sync(0xffffffffu, rs1, 1);
        rs1 += __shfl_xor_sync(0xffffffffu, rs1, 2);
        l0 = l0*cor0 + rs0;
        l1 = l1*cor1 + rs1;
        #pragma unroll
        for (int j = 0; j < 8; j++) {
            oacc[j][0] *= cor0; oacc[j][1] *= cor0;
            oacc[j][2] *= cor1; oacc[j][3] *= cor1;
        }

        #pragma unroll
        for (int t = 0; t < 4; t++) {
            uint32_t pah[4], pal[4];
            split2(sacc[2*t][0],   sacc[2*t][1],   pah[0], pal[0]);
            split2(sacc[2*t][2],   sacc[2*t][3],   pah[1], pal[1]);
            split2(sacc[2*t+1][0], sacc[2*t+1][1], pah[2], pal[2]);
            split2(sacc[2*t+1][2], sacc[2*t+1][3], pah[3], pal[3]);
            uint32_t vh[8][2], vl[8][2];
            #pragma unroll
            for (int u = 0; u < 4; u++) {
                uint32_t a = kbase + 2*ATILE + (16*t + (lane & 15))*ARS
                           + u*32 + ((lane >> 4) & 1)*16;
                uint32_t r0, r1, r2, r3;
                ldsm4t(r0, r1, r2, r3, a);
                vh[2*u][0] = r0; vh[2*u][1] = r1;
                vh[2*u+1][0] = r2; vh[2*u+1][1] = r3;
                ldsm4t(r0, r1, r2, r3, a + ATILE);
                vl[2*u][0] = r0; vl[2*u][1] = r1;
                vl[2*u+1][0] = r2; vl[2*u+1][1] = r3;
            }
            #pragma unroll
            for (int j = 0; j < 8; j++) {
                mma16816(oacc[j], pah, vh[j]);
                mma16816(oacc[j], pah, vl[j]);
                mma16816(oacc[j], pal, vh[j]);
            }
        }
        __syncthreads();
        if (kb + 2 < nt) load_kv(kb + 2, s);
    }

    const float inv0 = 1.0f / l0, inv1 = 1.0f / l1;
    const size_t tok0 = tokbase + qt*64 + wid*16 + gr;
    #pragma unroll
    for (int j = 0; j < 8; j++) {
        int col = colq + j*8 + cc*2;
        uint32_t hh, ll;
        split2(oacc[j][0]*inv0, oacc[j][1]*inv0, hh, ll);
        size_t p0 = (tok0*EMB + col) >> 1;
        Oh[p0] = hh; Ol[p0] = ll;
        split2(oacc[j][2]*inv1, oacc[j][3]*inv1, hh, ll);
        size_t p1 = ((tok0 + 8)*EMB + col) >> 1;
        Oh[p1] = hh; Ol[p1] = ll;
    }
}

// ---------------- launch -----------------------------------------------------
extern "C" void kernel_launch(void* const* d_in, const int* in_sizes, int n_in,
                              void* d_out, int out_size)
{
    const float* x      = (const float*)d_in[0];
    const float* ln1_s  = (const float*)d_in[1];
    const float* ln1_b  = (const float*)d_in[2];
    const float* Wq     = (const float*)d_in[3];
    const float* Wk     = (const float*)d_in[4];
    const float* Wv     = (const float*)d_in[5];
    const float* Wo     = (const float*)d_in[6];
    const float* bo     = (const float*)d_in[7];
    const float* ln2_s  = (const float*)d_in[8];
    const float* ln2_b  = (const float*)d_in[9];
    const float* W1     = (const float*)d_in[10];
    const float* b1     = (const float*)d_in[11];
    const float* W2     = (const float*)d_in[12];
    const float* b2     = (const float*)d_in[13];
    float* out = (float*)d_out;

    void* parena = nullptr;
    cudaGetSymbolAddress(&parena, g_arena);
    float* arena = (float*)parena;

    uint32_t* qkvh = (uint32_t*)arena;
    uint32_t* qkvl = (uint32_t*)(arena + (size_t)MTOK*1536);
    float* x1  = arena + OF_X1;
    uint32_t* h_hi   = (uint32_t*)(arena + OF_HB + HSLOT*0);
    uint32_t* h_lo   = (uint32_t*)(arena + OF_HB + HSLOT*1);
    uint32_t* h2_hi  = (uint32_t*)(arena + OF_HB + HSLOT*2);
    uint32_t* h2_lo  = (uint32_t*)(arena + OF_HB + HSLOT*3);
    uint32_t* ctx_hi = (uint32_t*)(arena + OF_HB + HSLOT*4);
    uint32_t* ctx_lo = (uint32_t*)(arena + OF_HB + HSLOT*5);
    uint32_t* ffn_hi = (uint32_t*)(arena + OF_FFN);
    uint32_t* ffn_lo = (uint32_t*)(arena + OF_FFN + FSLOT);

    uint32_t* wb   = (uint32_t*)(arena + OF_WT);
    uint32_t* wqvh = wb;                  uint32_t* wqvl = wqvh + PLANE_Q;
    uint32_t* woh  = wqvl + PLANE_Q;      uint32_t* wol  = woh  + PLANE_E;
    uint32_t* w1h  = wol  + PLANE_E;      uint32_t* w1l  = w1h  + PLANE_F;
    uint32_t* w2h  = w1l  + PLANE_F;      uint32_t* w2l  = w2h  + PLANE_F;

    cudaFuncSetAttribute(hgemm<0,0>, cudaFuncAttributeMaxDynamicSharedMemorySize, GEMM_SMEM);
    cudaFuncSetAttribute(hgemm<0,1>, cudaFuncAttributeMaxDynamicSharedMemorySize, GEMM_SMEM);
    cudaFuncSetAttribute(hgemm<1,1>, cudaFuncAttributeMaxDynamicSharedMemorySize, GEMM_SMEM);
    cudaFuncSetAttribute(attn_mma,   cudaFuncAttributeMaxDynamicSharedMemorySize, ATTN_SMEM);

    dim3 pE(EMB/32, EMB/32);
    dim3 gQ(QKS/256, MTOK/128);     // (12, 32)
    dim3 gE(EMB/256, MTOK/128);     // (4, 32)
    dim3 gF(FF/256,  MTOK/128);     // (16, 32)

    // weight prepass (qkv + wo)
    split_transpose<<<pE, 256>>>(Wq, wqvh,            wqvl,            EMB, EMB);
    split_transpose<<<pE, 256>>>(Wk, wqvh + 1024*512, wqvl + 1024*512, EMB, EMB);
    split_transpose<<<pE, 256>>>(Wv, wqvh + 2048*512, wqvl + 2048*512, EMB, EMB);
    split_transpose<<<pE, 256>>>(Wo, woh, wol, EMB, EMB);
    // LN1 -> h planes
    ln_planes<<<MTOK, 256>>>(x, ln1_s, ln1_b, h_hi, h_lo);
    // fused QKV projection -> bf16 planes
    hgemm<0,1><<<gQ, 256, GEMM_SMEM>>>((__nv_bfloat16*)h_hi, (__nv_bfloat16*)h_lo,
        (__nv_bfloat16*)wqvh, (__nv_bfloat16*)wqvl, nullptr, nullptr, nullptr, qkvh, qkvl,
        MTOK, QKS, EMB);
    // tensor-core causal flash attention -> ctx planes
    attn_mma<<<dim3(SEQ/64, HEADS, BATCH), 128, ATTN_SMEM>>>(
        (const __nv_bfloat16*)qkvh, (const __nv_bfloat16*)qkvl, ctx_hi, ctx_lo);
    // x1 = x + ctx@Wo + bo
    hgemm<0,0><<<gE, 256, GEMM_SMEM>>>((__nv_bfloat16*)ctx_hi, (__nv_bfloat16*)ctx_lo,
        (__nv_bfloat16*)woh, (__nv_bfloat16*)wol, bo, x, x1, nullptr, nullptr,
        MTOK, EMB, EMB);
    // LN2 -> h2 planes
    ln_planes<<<MTOK, 256>>>(x1, ln2_s, ln2_b, h2_hi, h2_lo);
    // W1 prepass
    split_transpose<<<dim3(FF/32,  EMB/32), 256>>>(W1, w1h, w1l, EMB, FF);
    // FFN up + GELU -> ffn planes
    hgemm<1,1><<<gF, 256, GEMM_SMEM>>>((__nv_bfloat16*)h2_hi, (__nv_bfloat16*)h2_lo,
        (__nv_bfloat16*)w1h, (__nv_bfloat16*)w1l, b1, nullptr, nullptr, ffn_hi, ffn_lo,
        MTOK, FF, EMB);
    // W2 prepass
    split_transpose<<<dim3(EMB/32, FF/32 ), 256>>>(W2, w2h, w2l, FF, EMB);
    // out = x1 + ffn@W2 + b2
    hgemm<0,0><<<gE, 256, GEMM_SMEM>>>((__nv_bfloat16*)ffn_hi, (__nv_bfloat16*)ffn_lo,
        (__nv_bfloat16*)w2h, (__nv_bfloat16*)w2l, b2, x1, out, nullptr, nullptr,
        MTOK, EMB, FF);
}

// round 15
// speedup vs baseline: 1.0235x; 1.0064x over previous
#include <cuda_runtime.h>
#include <cuda_bf16.h>
#include <math.h>
#include <stdint.h>

#define EMB   1024
#define SEQ   2048
#define BATCH 2
#define MTOK  (BATCH*SEQ)   // 4096
#define FF    4096
#define HEADS 16
#define HD    64
#define QKS   3072          // fused qkv col count

// ---------------- arena ------------------------------------------------------
#define SLOT    ((size_t)MTOK*EMB)
#define HSLOT   (SLOT/2)
#define FSLOT   ((size_t)MTOK*FF/2)
#define PLANE_Q 1572864ull
#define PLANE_E 524288ull
#define PLANE_F 2097152ull
#define OF_X1   (SLOT*3)
#define OF_HB   (SLOT*4)
#define OF_FFN  (OF_HB + HSLOT*6)
#define OF_WT   (OF_FFN + FSLOT*2)
__device__ float g_arena[OF_WT + 2ull*PLANE_Q + 2ull*PLANE_E + 4ull*PLANE_F];

// ---------------- helpers ----------------------------------------------------
__device__ __forceinline__ void split2(float x0, float x1, uint32_t& hi, uint32_t& lo)
{
    __nv_bfloat16 h0 = __float2bfloat16(x0);
    __nv_bfloat16 h1 = __float2bfloat16(x1);
    __nv_bfloat16 l0 = __float2bfloat16(x0 - __bfloat162float(h0));
    __nv_bfloat16 l1 = __float2bfloat16(x1 - __bfloat162float(h1));
    hi = (uint32_t)__bfloat16_as_ushort(h0) | ((uint32_t)__bfloat16_as_ushort(h1) << 16);
    lo = (uint32_t)__bfloat16_as_ushort(l0) | ((uint32_t)__bfloat16_as_ushort(l1) << 16);
}

__device__ __forceinline__ float gelu_f(float x)
{
    float x3 = x*x*x;
    float t  = tanhf(0.7978845608028654f*(x + 0.044715f*x3));
    return 0.5f*x*(1.0f + t);
}

__device__ __forceinline__ uint32_t smem_u32(const void* p)
{
    return (uint32_t)__cvta_generic_to_shared(p);
}

#define CP16(dst, src) \
    asm volatile("cp.async.cg.shared.global [%0], [%1], 16;\n" :: "r"(dst), "l"(src))
#define CP_COMMIT() asm volatile("cp.async.commit_group;\n" ::: "memory")
#define CP_WAIT0()  asm volatile("cp.async.wait_group 0;\n" ::: "memory")
#define CP_WAIT1()  asm volatile("cp.async.wait_group 1;\n" ::: "memory")

__device__ __forceinline__ void mma16816(float* c, const uint32_t* a, const uint32_t* b)
{
    asm volatile(
        "mma.sync.aligned.m16n8k16.row.col.f32.bf16.bf16.f32 "
        "{%0,%1,%2,%3},{%4,%5,%6,%7},{%8,%9},{%0,%1,%2,%3};"
        : "+f"(c[0]), "+f"(c[1]), "+f"(c[2]), "+f"(c[3])
        : "r"(a[0]), "r"(a[1]), "r"(a[2]), "r"(a[3]), "r"(b[0]), "r"(b[1]));
}

__device__ __forceinline__ void ldsm4(uint32_t& r0, uint32_t& r1, uint32_t& r2,
                                      uint32_t& r3, uint32_t addr)
{
    asm volatile("ldmatrix.sync.aligned.m8n8.x4.shared.b16 {%0,%1,%2,%3}, [%4];"
        : "=r"(r0), "=r"(r1), "=r"(r2), "=r"(r3) : "r"(addr));
}

__device__ __forceinline__ void ldsm4t(uint32_t& r0, uint32_t& r1, uint32_t& r2,
                                       uint32_t& r3, uint32_t addr)
{
    asm volatile("ldmatrix.sync.aligned.m8n8.x4.trans.shared.b16 {%0,%1,%2,%3}, [%4];"
        : "=r"(r0), "=r"(r1), "=r"(r2), "=r"(r3) : "r"(addr));
}

// ---------------- weight prepass: W[K][N] -> Wt hi/lo [n][k] bf16 -----------
__global__ __launch_bounds__(256)
void split_transpose(const float* __restrict__ W, uint32_t* __restrict__ Oh,
                     uint32_t* __restrict__ Ol, int K, int N)
{
    __shared__ float t[32][33];
    int n0 = blockIdx.x*32, k0 = blockIdx.y*32;
    int tid = threadIdx.x;
    #pragma unroll
    for (int i = 0; i < 4; i++) {
        int idx = tid + 256*i;
        int r = idx >> 5, c = idx & 31;
        t[r][c] = W[(size_t)(k0 + r)*N + n0 + c];
    }
    __syncthreads();
    #pragma unroll
    for (int i = 0; i < 2; i++) {
        int s = tid + 256*i;
        int n = s >> 4, p = s & 15;
        uint32_t h, l;
        split2(t[2*p][n], t[2*p+1][n], h, l);
        size_t off = (size_t)(n0 + n)*(K >> 1) + (k0 >> 1) + p;
        Oh[off] = h; Ol[off] = l;
    }
}

// ---------------- HMMA bf16x3 GEMM: 128x256 CTA tile, 64x64 warp tile -------
#define GRS   144
#define ATB   (128*GRS)       // 18432 (A plane)
#define BTB   (256*GRS)       // 36864 (B plane)
#define GSTG  (2*ATB + 2*BTB) // 110592
#define OFF_BH (2*ATB)        // 36864
#define GEMM_SMEM (2*GSTG)    // 221184

template<int ACT, int OUTP>
__global__ __launch_bounds__(256)
void hgemm(const __nv_bfloat16* __restrict__ Ah_, const __nv_bfloat16* __restrict__ Al_,
           const __nv_bfloat16* __restrict__ Bh_, const __nv_bfloat16* __restrict__ Bl_,
           const float* __restrict__ bias, const float* __restrict__ res,
           float* __restrict__ Cf, uint32_t* __restrict__ Ch, uint32_t* __restrict__ Cl,
           int M, int N, int K)
{
    extern __shared__ char smem[];
    const uint32_t sb = smem_u32(smem);
    const int tid  = threadIdx.x;
    const int wid  = tid >> 5;
    const int lane = tid & 31;
    const int bn   = blockIdx.x * 256;
    const int bm   = blockIdx.y * 128;
    const int wm   = (wid >> 2) * 64;
    const int wn   = (wid & 3) * 64;
    const int gr   = lane >> 2;
    const int cc   = lane & 3;
    const int nc   = K / 64;

    float acc[4][8][4];
    #pragma unroll
    for (int i = 0; i < 4; i++)
        #pragma unroll
        for (int j = 0; j < 8; j++)
            #pragma unroll
            for (int r = 0; r < 4; r++) acc[i][j][r] = 0.f;

    auto load_chunk = [&](int ck, int s) {
        const uint32_t stb = sb + s*GSTG;
        const int k0 = ck * 64;
        #pragma unroll
        for (int i = 0; i < 4; i++) {
            int id = tid + 256*i;
            int r = id >> 3; int c = id & 7;
            uint32_t d = stb + r*GRS + c*16;
            size_t ga = (size_t)(bm + r)*K + k0 + c*8;
            CP16(d,       Ah_ + ga);
            CP16(d + ATB, Al_ + ga);
        }
        #pragma unroll
        for (int i = 0; i < 8; i++) {
            int id = tid + 256*i;
            int r = id >> 3; int c = id & 7;
            uint32_t d = stb + OFF_BH + r*GRS + c*16;
            size_t gb = (size_t)(bn + r)*K + k0 + c*8;
            CP16(d,       Bh_ + gb);
            CP16(d + BTB, Bl_ + gb);
        }
        CP_COMMIT();
    };

    const uint32_t aoff = (uint32_t)((wm + (lane & 15))*GRS + ((lane >> 4) & 1)*16);
    const uint32_t boff = (uint32_t)((wn + (lane & 15))*GRS + ((lane >> 4) & 1)*16);

    load_chunk(0, 0);
    if (nc > 1) load_chunk(1, 1);

    for (int i = 0; i < nc; i++) {
        const int s = i & 1;
        if (i + 1 < nc) CP_WAIT1(); else CP_WAIT0();
        __syncthreads();

        const uint32_t stb = sb + s*GSTG;
        #pragma unroll
        for (int t = 0; t < 4; t++) {
            const uint32_t ka = t*32;
            uint32_t ah[4][4], al[4][4];
            #pragma unroll
            for (int mi = 0; mi < 4; mi++) {
                ldsm4(ah[mi][0], ah[mi][1], ah[mi][2], ah[mi][3],
                      stb + aoff + mi*16*GRS + ka);
                ldsm4(al[mi][0], al[mi][1], al[mi][2], al[mi][3],
                      stb + ATB + aoff + mi*16*GRS + ka);
            }
            #pragma unroll
            for (int h = 0; h < 2; h++) {
                uint32_t bh[4][2], bl[4][2];
                #pragma unroll
                for (int p = 0; p < 2; p++) {
                    uint32_t a = stb + OFF_BH + boff + (h*32 + p*16)*GRS + ka;
                    uint32_t r0, r1, r2, r3;
                    ldsm4(r0, r1, r2, r3, a);
                    bh[2*p][0] = r0; bh[2*p][1] = r2;
                    bh[2*p+1][0] = r1; bh[2*p+1][1] = r3;
                    ldsm4(r0, r1, r2, r3, a + BTB);
                    bl[2*p][0] = r0; bl[2*p][1] = r2;
                    bl[2*p+1][0] = r1; bl[2*p+1][1] = r3;
                }
                #pragma unroll
                for (int mi = 0; mi < 4; mi++)
                    #pragma unroll
                    for (int nj = 0; nj < 4; nj++) {
                        float* a4 = acc[mi][h*4 + nj];
                        mma16816(a4, ah[mi], bh[nj]);
                        mma16816(a4, ah[mi], bl[nj]);
                        mma16816(a4, al[mi], bh[nj]);
                    }
            }
        }
        __syncthreads();
        if (i + 2 < nc) load_chunk(i + 2, s);
    }

    #pragma unroll
    for (int mi = 0; mi < 4; mi++) {
        int r0 = bm + wm + mi*16 + gr;
        #pragma unroll
        for (int nj = 0; nj < 8; nj++) {
            int col = bn + wn + nj*8 + cc*2;
            float2 v0, v1;
            v0.x = acc[mi][nj][0]; v0.y = acc[mi][nj][1];
            v1.x = acc[mi][nj][2]; v1.y = acc[mi][nj][3];
            if (bias) {
                float2 bv = *(const float2*)(bias + col);
                v0.x += bv.x; v0.y += bv.y; v1.x += bv.x; v1.y += bv.y;
            }
            if (ACT == 1) {
                v0.x = gelu_f(v0.x); v0.y = gelu_f(v0.y);
                v1.x = gelu_f(v1.x); v1.y = gelu_f(v1.y);
            }
            if (res) {
                float2 ra = *(const float2*)(res + (size_t)r0*N + col);
                float2 rb = *(const float2*)(res + (size_t)(r0+8)*N + col);
                v0.x += ra.x; v0.y += ra.y; v1.x += rb.x; v1.y += rb.y;
            }
            if (OUTP == 0) {
                *(float2*)(Cf + (size_t)r0*N + col)     = v0;
                *(float2*)(Cf + (size_t)(r0+8)*N + col) = v1;
            } else {
                uint32_t hh, ll;
                split2(v0.x, v0.y, hh, ll);
                size_t p0 = ((size_t)r0*N + col) >> 1;
                Ch[p0] = hh; Cl[p0] = ll;
                split2(v1.x, v1.y, hh, ll);
                size_t p1 = ((size_t)(r0+8)*N + col) >> 1;
                Ch[p1] = hh; Cl[p1] = ll;
            }
        }
    }
}

// ---------------- LayerNorm (warp per row) -> bf16 hi/lo planes -------------
__global__ __launch_bounds__(256)
void ln_planes(const float* __restrict__ x, const float* __restrict__ scale,
               const float* __restrict__ shift,
               uint32_t* __restrict__ yh, uint32_t* __restrict__ yl)
{
    const int warp = threadIdx.x >> 5, lane = threadIdx.x & 31;
    const int row  = blockIdx.x*8 + warp;
    const float4* xr = (const float4*)(x + (size_t)row*EMB);

    float4 v[8];
    float s = 0.f, ss = 0.f;
    #pragma unroll
    for (int i = 0; i < 8; i++) {
        v[i] = xr[lane + 32*i];
        s  += v[i].x + v[i].y + v[i].z + v[i].w;
        ss += v[i].x*v[i].x + v[i].y*v[i].y + v[i].z*v[i].z + v[i].w*v[i].w;
    }
    #pragma unroll
    for (int o = 16; o > 0; o >>= 1) {
        s  += __shfl_xor_sync(0xffffffffu, s,  o);
        ss += __shfl_xor_sync(0xffffffffu, ss, o);
    }
    const float mean = s * (1.0f/EMB);
    const float rstd = rsqrtf(ss * (1.0f/EMB) - mean*mean + 1e-5f);

    #pragma unroll
    for (int i = 0; i < 8; i++) {
        const int c4 = lane + 32*i;
        float4 sc = ((const float4*)scale)[c4];
        float4 sh = ((const float4*)shift)[c4];
        float o0 = sc.x*(v[i].x-mean)*rstd + sh.x;
        float o1 = sc.y*(v[i].y-mean)*rstd + sh.y;
        float o2 = sc.z*(v[i].z-mean)*rstd + sh.z;
        float o3 = sc.w*(v[i].w-mean)*rstd + sh.w;
        uint32_t h0, l0, h1, l1;
        split2(o0, o1, h0, l0);
        split2(o2, o3, h1, l1);
        size_t p = (size_t)row*(EMB/2) + c4*2;
        uint2 hv; hv.x = h0; hv.y = h1;
        uint2 lv; lv.x = l0; lv.y = l1;
        *(uint2*)(yh + p) = hv;
        *(uint2*)(yl + p) = lv;
    }
}

// ---------------- Tensor-core flash attention (R9 config) -------------------
#define ARS   144
#define ATILE (64*ARS)      // 9216
#define ASTG  (4*ATILE)     // 36864
#define ATTN_SMEM (2*ASTG)  // 73728

__global__ __launch_bounds__(128)
void attn_mma(const __nv_bfloat16* __restrict__ Ph, const __nv_bfloat16* __restrict__ Pl,
              uint32_t* __restrict__ Oh, uint32_t* __restrict__ Ol)
{
    extern __shared__ char smem[];
    const uint32_t sb = smem_u32(smem);
    const int qt  = blockIdx.x;
    const int hd  = blockIdx.y;
    const int b   = blockIdx.z;
    const int tid = threadIdx.x;
    const int wid = tid >> 5, lane = tid & 31;
    const int gr  = lane >> 2, cc = lane & 3;
    const int nt  = qt + 1;
    const size_t tokbase = (size_t)b * SEQ;
    const int colq = hd * HD;

    #pragma unroll
    for (int i = 0; i < 4; i++) {
        int id = tid + 128*i; int r = id >> 3; int c = id & 7;
        size_t g = (tokbase + qt*64 + r)*QKS + colq + c*8;
        CP16(sb + r*ARS + c*16,         Ph + g);
        CP16(sb + ATILE + r*ARS + c*16, Pl + g);
    }
    CP_COMMIT(); CP_WAIT0();
    __syncthreads();

    uint32_t qfh[4][4], qfl[4][4];
    {
        const uint32_t qoff = (uint32_t)((wid*16 + (lane & 15))*ARS + ((lane >> 4) & 1)*16);
        #pragma unroll
        for (int t = 0; t < 4; t++) {
            ldsm4(qfh[t][0], qfh[t][1], qfh[t][2], qfh[t][3], sb + qoff + t*32);
            ldsm4(qfl[t][0], qfl[t][1], qfl[t][2], qfl[t][3], sb + ATILE + qoff + t*32);
        }
    }
    __syncthreads();

    float oacc[8][4];
    #pragma unroll
    for (int j = 0; j < 8; j++)
        #pragma unroll
        for (int r = 0; r < 4; r++) oacc[j][r] = 0.f;
    float m0 = -INFINITY, m1 = -INFINITY, l0 = 0.f, l1 = 0.f;

    auto load_kv = [&](int kb, int s) {
        const uint32_t base = sb + s*ASTG;
        #pragma unroll
        for (int i = 0; i < 4; i++) {
            int id = tid + 128*i; int r = id >> 3; int c = id & 7;
            size_t g = (tokbase + kb*64 + r)*QKS + colq + c*8;
            CP16(base           + r*ARS + c*16, Ph + g + 1024);
            CP16(base + ATILE   + r*ARS + c*16, Pl + g + 1024);
            CP16(base + 2*ATILE + r*ARS + c*16, Ph + g + 2048);
            CP16(base + 3*ATILE + r*ARS + c*16, Pl + g + 2048);
        }
        CP_COMMIT();
    };

    load_kv(0, 0);
    if (nt > 1) load_kv(1, 1);

    const uint32_t koff = (uint32_t)(((lane & 15))*ARS + ((lane >> 4) & 1)*16);
    const int rowg0 = qt*64 + wid*16 + gr;
    const int rowg1 = rowg0 + 8;

    for (int kb = 0; kb < nt; kb++) {
        const int s = kb & 1;
        if (kb + 1 < nt) CP_WAIT1(); else CP_WAIT0();
        __syncthreads();
        const uint32_t kbase = sb + s*ASTG;

        float sacc[8][4];
        #pragma unroll
        for (int j = 0; j < 8; j++)
            #pragma unroll
            for (int r = 0; r < 4; r++) sacc[j][r] = 0.f;

        #pragma unroll
        for (int t = 0; t < 4; t++) {
            uint32_t bh[8][2], bl[8][2];
            #pragma unroll
            for (int p = 0; p < 4; p++) {
                uint32_t a = kbase + p*16*ARS + koff + t*32;
                uint32_t r0, r1, r2, r3;
                ldsm4(r0, r1, r2, r3, a);
                bh[2*p][0] = r0; bh[2*p][1] = r2;
                bh[2*p+1][0] = r1; bh[2*p+1][1] = r3;
                ldsm4(r0, r1, r2, r3, a + ATILE);
                bl[2*p][0] = r0; bl[2*p][1] = r2;
                bl[2*p+1][0] = r1; bl[2*p+1][1] = r3;
            }
            #pragma unroll
            for (int j = 0; j < 8; j++) {
                mma16816(sacc[j], qfh[t], bh[j]);
                mma16816(sacc[j], qfh[t], bl[j]);
                mma16816(sacc[j], qfl[t], bh[j]);
            }
        }

        const bool diag = (kb == qt);
        float rmax0 = -INFINITY, rmax1 = -INFINITY;
        #pragma unroll
        for (int j = 0; j < 8; j++) {
            int c0 = kb*64 + j*8 + cc*2;
            float v0 = sacc[j][0]*0.125f, v1 = sacc[j][1]*0.125f;
            float v2 = sacc[j][2]*0.125f, v3 = sacc[j][3]*0.125f;
            if (diag) {
                if (c0     > rowg0) v0 = -INFINITY;
                if (c0 + 1 > rowg0) v1 = -INFINITY;
                if (c0     > rowg1) v2 = -INFINITY;
                if (c0 + 1 > rowg1) v3 = -INFINITY;
            }
            sacc[j][0] = v0; sacc[j][1] = v1; sacc[j][2] = v2; sacc[j][3] = v3;
            rmax0 = fmaxf(rmax0, fmaxf(v0, v1));
            rmax1 = fmaxf(rmax1, fmaxf(v2, v3));
        }
        rmax0 = fmaxf(rmax0, __shfl_xor_sync(0xffffffffu, rmax0, 1));
        rmax0 = fmaxf(rmax0, __shfl_xor_sync(0xffffffffu, rmax0, 2));
        rmax1 = fmaxf(rmax1, __shfl_xor_sync(0xffffffffu, rmax1, 1));
        rmax1 = fmaxf(rmax1, __shfl_xor_sync(0xffffffffu, rmax1, 2));
        float mn0 = fmaxf(m0, rmax0), mn1 = fmaxf(m1, rmax1);
        float cor0 = __expf(m0 - mn0), cor1 = __expf(m1 - mn1);
        m0 = mn0; m1 = mn1;
        float rs0 = 0.f, rs1 = 0.f;
        #pragma unroll
        for (int j = 0; j < 8; j++) {
            float p0 = __expf(sacc[j][0] - mn0);
            float p1 = __expf(sacc[j][1] - mn0);
            float p2 = __expf(sacc[j][2] - mn1);
            float p3 = __expf(sacc[j][3] - mn1);
            sacc[j][0] = p0; sacc[j][1] = p1; sacc[j][2] = p2; sacc[j][3] = p3;
            rs0 += p0 + p1; rs1 += p2 + p3;
        }
        rs0 += __shfl_xor_sync(0xffffffffu, rs0, 1);
        rs0 += __shfl_xor_sync(0xffffffffu, rs0, 2);
        rs1 += __shfl_xor_sync(0xffffffffu, rs1, 1);
        rs1 += __shfl_xor_sync(0xffffffffu, rs1, 2);
        l0 = l0*cor0 + rs0;
        l1 = l1*cor1 + rs1;
        #pragma unroll
        for (int j = 0; j < 8; j++) {
            oacc[j][0] *= cor0; oacc[j][1] *= cor0;
            oacc[j][2] *= cor1; oacc[j][3] *= cor1;
        }

        #pragma unroll
        for (int t = 0; t < 4; t++) {
            uint32_t pah[4], pal[4];
            split2(sacc[2*t][0],   sacc[2*t][1],   pah[0], pal[0]);
            split2(sacc[2*t][2],   sacc[2*t][3],   pah[1], pal[1]);
            split2(sacc[2*t+1][0], sacc[2*t+1][1], pah[2], pal[2]);
            split2(sacc[2*t+1][2], sacc[2*t+1][3], pah[3], pal[3]);
            uint32_t vh[8][2], vl[8][2];
            #pragma unroll
            for (int u = 0; u < 4; u++) {
                uint32_t a = kbase + 2*ATILE + (16*t + (lane & 15))*ARS
                           + u*32 + ((lane >> 4) & 1)*16;
                uint32_t r0, r1, r2, r3;
                ldsm4t(r0, r1, r2, r3, a);
                vh[2*u][0] = r0; vh[2*u][1] = r1;
                vh[2*u+1][0] = r2; vh[2*u+1][1] = r3;
                ldsm4t(r0, r1, r2, r3, a + ATILE);
                vl[2*u][0] = r0; vl[2*u][1] = r1;
                vl[2*u+1][0] = r2; vl[2*u+1][1] = r3;
            }
            #pragma unroll
            for (int j = 0; j < 8; j++) {
                mma16816(oacc[j], pah, vh[j]);
                mma16816(oacc[j], pah, vl[j]);
                mma16816(oacc[j], pal, vh[j]);
            }
        }
        __syncthreads();
        if (kb + 2 < nt) load_kv(kb + 2, s);
    }

    const float inv0 = 1.0f / l0, inv1 = 1.0f / l1;
    const size_t tok0 = tokbase + qt*64 + wid*16 + gr;
    #pragma unroll
    for (int j = 0; j < 8; j++) {
        int col = colq + j*8 + cc*2;
        uint32_t hh, ll;
        split2(oacc[j][0]*inv0, oacc[j][1]*inv0, hh, ll);
        size_t p0 = (tok0*EMB + col) >> 1;
        Oh[p0] = hh; Ol[p0] = ll;
        split2(oacc[j][2]*inv1, oacc[j][3]*inv1, hh, ll);
        size_t p1 = ((tok0 + 8)*EMB + col) >> 1;
        Oh[p1] = hh; Ol[p1] = ll;
    }
}

// ---------------- launch -----------------------------------------------------
extern "C" void kernel_launch(void* const* d_in, const int* in_sizes, int n_in,
                              void* d_out, int out_size)
{
    const float* x      = (const float*)d_in[0];
    const float* ln1_s  = (const float*)d_in[1];
    const float* ln1_b  = (const float*)d_in[2];
    const float* Wq     = (const float*)d_in[3];
    const float* Wk     = (const float*)d_in[4];
    const float* Wv     = (const float*)d_in[5];
    const float* Wo     = (const float*)d_in[6];
    const float* bo     = (const float*)d_in[7];
    const float* ln2_s  = (const float*)d_in[8];
    const float* ln2_b  = (const float*)d_in[9];
    const float* W1     = (const float*)d_in[10];
    const float* b1     = (const float*)d_in[11];
    const float* W2     = (const float*)d_in[12];
    const float* b2     = (const float*)d_in[13];
    float* out = (float*)d_out;

    void* parena = nullptr;
    cudaGetSymbolAddress(&parena, g_arena);
    float* arena = (float*)parena;

    uint32_t* qkvh = (uint32_t*)arena;
    uint32_t* qkvl = (uint32_t*)(arena + (size_t)MTOK*1536);
    float* x1  = arena + OF_X1;
    uint32_t* h_hi   = (uint32_t*)(arena + OF_HB + HSLOT*0);
    uint32_t* h_lo   = (uint32_t*)(arena + OF_HB + HSLOT*1);
    uint32_t* h2_hi  = (uint32_t*)(arena + OF_HB + HSLOT*2);
    uint32_t* h2_lo  = (uint32_t*)(arena + OF_HB + HSLOT*3);
    uint32_t* ctx_hi = (uint32_t*)(arena + OF_HB + HSLOT*4);
    uint32_t* ctx_lo = (uint32_t*)(arena + OF_HB + HSLOT*5);
    uint32_t* ffn_hi = (uint32_t*)(arena + OF_FFN);
    uint32_t* ffn_lo = (uint32_t*)(arena + OF_FFN + FSLOT);

    uint32_t* wb   = (uint32_t*)(arena + OF_WT);
    uint32_t* wqvh = wb;                  uint32_t* wqvl = wqvh + PLANE_Q;
    uint32_t* woh  = wqvl + PLANE_Q;      uint32_t* wol  = woh  + PLANE_E;
    uint32_t* w1h  = wol  + PLANE_E;      uint32_t* w1l  = w1h  + PLANE_F;
    uint32_t* w2h  = w1l  + PLANE_F;      uint32_t* w2l  = w2h  + PLANE_F;

    cudaFuncSetAttribute(hgemm<0,0>, cudaFuncAttributeMaxDynamicSharedMemorySize, GEMM_SMEM);
    cudaFuncSetAttribute(hgemm<0,1>, cudaFuncAttributeMaxDynamicSharedMemorySize, GEMM_SMEM);
    cudaFuncSetAttribute(hgemm<1,1>, cudaFuncAttributeMaxDynamicSharedMemorySize, GEMM_SMEM);
    cudaFuncSetAttribute(attn_mma,   cudaFuncAttributeMaxDynamicSharedMemorySize, ATTN_SMEM);

    dim3 pE(EMB/32, EMB/32);
    dim3 gQ(QKS/256, MTOK/128);     // (12, 32)
    dim3 gE(EMB/256, MTOK/128);     // (4, 32)
    dim3 gF(FF/256,  MTOK/128);     // (16, 32)

    // -------- side stream for weight prepass (fork/join inside capture) -----
    cudaStream_t s2;
    cudaStreamCreateWithFlags(&s2, cudaStreamNonBlocking);
    cudaEvent_t evFork, evQ, evO, evW1, evW2;
    cudaEventCreateWithFlags(&evFork, cudaEventDisableTiming);
    cudaEventCreateWithFlags(&evQ,    cudaEventDisableTiming);
    cudaEventCreateWithFlags(&evO,    cudaEventDisableTiming);
    cudaEventCreateWithFlags(&evW1,   cudaEventDisableTiming);
    cudaEventCreateWithFlags(&evW2,   cudaEventDisableTiming);

    cudaEventRecord(evFork, 0);
    cudaStreamWaitEvent(s2, evFork, 0);

    split_transpose<<<pE, 256, 0, s2>>>(Wq, wqvh,            wqvl,            EMB, EMB);
    split_transpose<<<pE, 256, 0, s2>>>(Wk, wqvh + 1024*512, wqvl + 1024*512, EMB, EMB);
    split_transpose<<<pE, 256, 0, s2>>>(Wv, wqvh + 2048*512, wqvl + 2048*512, EMB, EMB);
    cudaEventRecord(evQ, s2);
    split_transpose<<<pE, 256, 0, s2>>>(Wo, woh, wol, EMB, EMB);
    cudaEventRecord(evO, s2);
    split_transpose<<<dim3(FF/32,  EMB/32), 256, 0, s2>>>(W1, w1h, w1l, EMB, FF);
    cudaEventRecord(evW1, s2);
    split_transpose<<<dim3(EMB/32, FF/32 ), 256, 0, s2>>>(W2, w2h, w2l, FF, EMB);
    cudaEventRecord(evW2, s2);

    // -------- main stream ----------------------------------------------------
    // LN1 -> h planes (overlaps qkv prepass)
    ln_planes<<<MTOK/8, 256>>>(x, ln1_s, ln1_b, h_hi, h_lo);
    // fused QKV projection -> bf16 planes
    cudaStreamWaitEvent(0, evQ, 0);
    hgemm<0,1><<<gQ, 256, GEMM_SMEM>>>((__nv_bfloat16*)h_hi, (__nv_bfloat16*)h_lo,
        (__nv_bfloat16*)wqvh, (__nv_bfloat16*)wqvl, nullptr, nullptr, nullptr, qkvh, qkvl,
        MTOK, QKS, EMB);
    // tensor-core causal flash attention -> ctx planes
    attn_mma<<<dim3(SEQ/64, HEADS, BATCH), 128, ATTN_SMEM>>>(
        (const __nv_bfloat16*)qkvh, (const __nv_bfloat16*)qkvl, ctx_hi, ctx_lo);
    // x1 = x + ctx@Wo + bo
    cudaStreamWaitEvent(0, evO, 0);
    hgemm<0,0><<<gE, 256, GEMM_SMEM>>>((__nv_bfloat16*)ctx_hi, (__nv_bfloat16*)ctx_lo,
        (__nv_bfloat16*)woh, (__nv_bfloat16*)wol, bo, x, x1, nullptr, nullptr,
        MTOK, EMB, EMB);
    // LN2 -> h2 planes
    ln_planes<<<MTOK/8, 256>>>(x1, ln2_s, ln2_b, h2_hi, h2_lo);
    // FFN up + GELU -> ffn planes
    cudaStreamWaitEvent(0, evW1, 0);
    hgemm<1,1><<<gF, 256, GEMM_SMEM>>>((__nv_bfloat16*)h2_hi, (__nv_bfloat16*)h2_lo,
        (__nv_bfloat16*)w1h, (__nv_bfloat16*)w1l, b1, nullptr, nullptr, ffn_hi, ffn_lo,
        MTOK, FF, EMB);
    // out = x1 + ffn@W2 + b2
    cudaStreamWaitEvent(0, evW2, 0);
    hgemm<0,0><<<gE, 256, GEMM_SMEM>>>((__nv_bfloat16*)ffn_hi, (__nv_bfloat16*)ffn_lo,
        (__nv_bfloat16*)w2h, (__nv_bfloat16*)w2l, b2, x1, out, nullptr, nullptr,
        MTOK, EMB, FF);
}